// round 4
// baseline (speedup 1.0000x reference)
#include <cuda_runtime.h>
#include <math_constants.h>

// Problem constants
#define B_      256
#define N_      16
#define M_      128
#define V_      64
#define H_      256
#define K_      8
#define NP1_    17      // N + 1
#define KO_     136     // K * (N+1)
#define TYPES_  12
#define NCOMBO  180     // 15 spans x 12 types

// Output layout: new_d [B,M,V] floats, then new_v [B,40,3,V] zeros
#define OUT_D_ELEMS ((size_t)B_ * M_ * V_)
#define OUT_V_PER_B (40 * 3 * V_)   // 7680 floats per batch

#define GEMV_NT     544             // 136 outputs x 4 sub-chunks of 16 h
#define GEMV_BLOCKS (NCOMBO * 4)    // 720: combo x H-quadrant

// Scratch: partial dot products [quad][combo][o] (double) + presence flags.
__device__ double g_part[4 * NCOMBO * KO_];
__device__ int    g_flag[NCOMBO];

// ============================================================================
// Kernel 0: mark which (span,type) combos occur in this batch. 1 block.
// ============================================================================
__global__ void flag_kernel(const int* __restrict__ target_types,
                            const int* __restrict__ spans)
{
    const int tid = threadIdx.x;
    if (tid < NCOMBO) g_flag[tid] = 0;
    __syncthreads();
    const int t = target_types[tid];
    const int s = spans[tid];
    if (t != 20) g_flag[(s - 2) * TYPES_ + (t - 9)] = 1;
}

// ============================================================================
// Kernel 1: partial GEMV. grid = 720 (combo*4 + quad), block = 544.
// Thread = (output o, 16-h sub-chunk): 16 fully independent loads (MLP=16,
// zero dependent batches). Also grid-strides the new_v zero fill (8 MB).
// ============================================================================
__global__ __launch_bounds__(GEMV_NT, 3)
void gemv_kernel(const float* __restrict__ te_table,   // [21,H]
                 const float* __restrict__ W_sem,      // [15,12,H,KO]
                 float*       __restrict__ out)
{
    __shared__ float  s_te[64];
    __shared__ double s_part[GEMV_NT];

    const int tid   = threadIdx.x;
    const int combo = blockIdx.x >> 2;
    const int quad  = blockIdx.x & 3;

    // distributed new_v zero fill (independent of everything; issues early)
    {
        float4* __restrict__ dv = (float4*)(out + OUT_D_ELEMS);
        const int total4 = (B_ * OUT_V_PER_B) / 4;     // 491,520
        const float4 z = make_float4(0.f, 0.f, 0.f, 0.f);
        for (int i = blockIdx.x * GEMV_NT + tid; i < total4; i += GEMV_BLOCKS * GEMV_NT)
            dv[i] = z;
    }

    if (!g_flag[combo]) return;      // combo absent from this batch

    const int tt = 9 + combo % TYPES_;
    if (tid < 64) s_te[tid] = te_table[(size_t)tt * H_ + quad * 64 + tid];
    __syncthreads();

    const int o   = tid % KO_;       // output column 0..135
    const int sub = tid / KO_;       // 16-h sub-chunk 0..3
    const float* __restrict__ wp =
        W_sem + ((size_t)combo * H_ + (size_t)(quad * 64 + sub * 16)) * KO_ + o;
    const float* __restrict__ tp = s_te + sub * 16;

    float p[16];
    #pragma unroll
    for (int j = 0; j < 16; j++)
        p[j] = tp[j] * wp[(size_t)j * KO_];
    double s = 0.0;
    #pragma unroll
    for (int j = 0; j < 16; j += 2)
        s += (double)p[j] + (double)p[j + 1];
    s_part[tid] = s;
    __syncthreads();

    if (tid < KO_) {
        g_part[((size_t)quad * NCOMBO + combo) * KO_ + tid] =
            (s_part[tid] + s_part[tid + KO_]) +
            (s_part[tid + 2 * KO_] + s_part[tid + 3 * KO_]);
    }
}

// ============================================================================
// Kernel 2: per-batch selection (from partials) + template application.
// ============================================================================
__global__ __launch_bounds__(512, 2)
void apply_kernel(const float* __restrict__ decodings,     // [B,N,M,V]
                  const int*   __restrict__ target_types,  // [B]
                  const int*   __restrict__ spans,         // [B]
                  const float* __restrict__ b_sem,         // [15,12,KO]
                  const float* __restrict__ gumbel,        // [B,K,NP1]
                  float*       __restrict__ out)
{
    __shared__ int s_sel[K_];
    __shared__ int s_red[16];
    __shared__ int s_olen;

    const int b    = blockIdx.x;
    const int tid  = threadIdx.x;
    const int w    = tid >> 5;
    const int lane = tid & 31;
    const int tt   = target_types[b];
    const int sp   = spans[b];

    // ---- selection ----
    if (tt == 20) {
        if (tid < K_) s_sel[tid] = (tid == 0) ? 1 : 0;
    } else if (w < K_) {
        float val = -CUDART_INF_F;
        if (lane < NP1_ && lane <= sp) {
            const int combo = (sp - 2) * TYPES_ + (tt - 9);
            const int oo    = combo * KO_ + w * NP1_ + lane;
            const double sl = (g_part[(size_t)0 * NCOMBO * KO_ + oo]
                             + g_part[(size_t)1 * NCOMBO * KO_ + oo])
                            + (g_part[(size_t)2 * NCOMBO * KO_ + oo]
                             + g_part[(size_t)3 * NCOMBO * KO_ + oo]);
            val = (float)sl + __ldg(&b_sem[oo])
                + __ldg(&gumbel[((size_t)b * K_ + w) * NP1_ + lane]);
        }
        float bv = val;
        int   bn = lane;
        #pragma unroll
        for (int off = 16; off; off >>= 1) {
            float ov = __shfl_down_sync(0xffffffffu, bv, off);
            int   on = __shfl_down_sync(0xffffffffu, bn, off);
            if (ov > bv || (ov == bv && on < bn)) { bv = ov; bn = on; }
        }
        if (lane == 0) s_sel[w] = bn;
    }
    __syncthreads();

    // ---- fused speculative copy + olen (usually one iteration) ----
    const int c4    = tid & 15;    // float4 column within row (V=64 -> 16 float4)
    const int rbase = tid >> 4;    // base row 0..31
    int idx = 0;

    for (int k = 0; k < K_; k++) {
        if (idx >= M_) break;
        const int n = s_sel[k];
        if (n == 0) continue;

        const float4* __restrict__ tile4 =
            (const float4*)(decodings + ((size_t)b * N_ + (size_t)(n - 1)) * (M_ * V_));
        float4* __restrict__ out4 =
            (float4*)(out + ((size_t)b * M_ + idx) * V_);

        float4 v[4];
        #pragma unroll
        for (int j = 0; j < 4; j++)
            v[j] = tile4[(rbase + 32 * j) * 16 + c4];

        int local = 0;
        #pragma unroll
        for (int j = 0; j < 4; j++) {
            const int row = rbase + 32 * j;
            if (idx + row < M_)
                out4[row * 16 + c4] = v[j];
            // row non-pad iff max over v>0 of d[row][v] > d[row][0]
            float m = (c4 == 0) ? fmaxf(fmaxf(v[j].y, v[j].z), v[j].w)
                                : fmaxf(fmaxf(v[j].x, v[j].y), fmaxf(v[j].z, v[j].w));
            #pragma unroll
            for (int off = 1; off < 16; off <<= 1)
                m = fmaxf(m, __shfl_xor_sync(0xffffffffu, m, off));
            const float d0 = __shfl_sync(0xffffffffu, v[j].x, lane & 16);
            if (m > d0) local = row + 1;
        }
        #pragma unroll
        for (int off = 16; off; off >>= 1)
            local = max(local, __shfl_down_sync(0xffffffffu, local, off));
        if (lane == 0) s_red[w] = local;
        __syncthreads();
        if (tid == 0) {
            int o = 0;
            #pragma unroll
            for (int i = 0; i < 16; i++) o = max(o, s_red[i]);
            s_olen = o;
        }
        __syncthreads();
        idx += min(s_olen, M_ - idx);
    }

    // ---- zero fill tail of new_d ----
    const float4 z = make_float4(0.f, 0.f, 0.f, 0.f);
    float* __restrict__ dst = out + ((size_t)b * M_ + idx) * V_;
    const int rem4 = (M_ - idx) * (V_ / 4);
    for (int i = tid; i < rem4; i += 512)
        ((float4*)dst)[i] = z;
}

extern "C" void kernel_launch(void* const* d_in, const int* in_sizes, int n_in,
                              void* d_out, int out_size)
{
    (void)in_sizes; (void)n_in; (void)out_size;
    const float* decodings    = (const float*)d_in[0];
    // d_in[1] = variables : unused (new_v is all zeros)
    const int*   target_types = (const int*)d_in[2];
    const int*   spans        = (const int*)d_in[3];
    const float* te_table     = (const float*)d_in[4];
    const float* W_sem        = (const float*)d_in[5];
    const float* b_sem        = (const float*)d_in[6];
    const float* gumbel       = (const float*)d_in[7];
    float*       out          = (float*)d_out;

    flag_kernel<<<1, B_>>>(target_types, spans);
    gemv_kernel<<<GEMV_BLOCKS, GEMV_NT>>>(te_table, W_sem, out);
    apply_kernel<<<B_, 512>>>(decodings, target_types, spans, b_sem, gumbel, out);
}